// round 15
// baseline (speedup 1.0000x reference)
#include <cuda_runtime.h>
#include <cstdint>

#define MM    128   // padded image side
#define NP    64    // patch side
#define NC    4     // channels / positions
#define C0    32    // (M - N) / 2
#define WROW0 11    // first staged image row (fixed layout)
#define WROWS 108   // stage capacity rows 11..118
#define WCOL0 8     // first staged image col (16B-aligned)
#define WCOLS 112   // stage capacity cols 8..119 (EVEN -> tap parity is k-invariant)

__device__ __forceinline__ uint32_t smem_u32(const void* p) {
    uint32_t a;
    asm("{ .reg .u64 t; cvta.to.shared.u64 t, %1; cvt.u32.u64 %0, t; }"
        : "=r"(a) : "l"(p));
    return a;
}

// One CTA per image (R14 shell). Compute remap: block (2, 32, 8) ->
// tx = channel pair, ty = COLUMN PAIR, tz = 8-row band. Each thread does
// 2 cols x 2 ch per row: taps via 2 aligned LDS.64 per channel (cols of a
// pair share wx exactly; 2x2 taps live in a 4-float span, parity-selected),
// output assembled into one contiguous STG.128 per lane via a pair shuffle.
// Halves L1 ops per output byte vs R14 while keeping 64 warps/SM.
__global__ __launch_bounds__(512, 4)
void extract_patches_kernel(const float* __restrict__ img,
                            const float* __restrict__ pos,
                            float* __restrict__ out)
{
    __shared__ __align__(16) float stage[WROWS * WCOLS];   // 48384 B
    __shared__ float spos[2 * NC];
    __shared__ int   sbnd[4];        // r_lo, r_hi, q_lo, q_hi

    const int b = blockIdx.x;
    const float* I = img + (size_t)b * (MM * MM);

    const int lid  = threadIdx.x + 2 * threadIdx.y + 64 * threadIdx.z;
    const int wid  = lid >> 5;     // 16 warps
    const int lane = lid & 31;

    // One warp computes the dynamic window bounds + stages positions.
    if (wid == 0) {
        if (lane < 2 * NC)
            spos[lane] = __ldg(pos + (size_t)b * (2 * NC) + lane);
        __syncwarp();
        if (lane == 0) {
            int ymin = MM, ymax = 0, xmin = MM, xmax = 0;
#pragma unroll
            for (int c = 0; c < NC; c++) {
                // Pad one cell each side for per-element floor rounding slack.
                int yb = (int)floorf((float)C0 + spos[NC + c]);
                int xb = (int)floorf((float)C0 + spos[c]);
                ymin = min(ymin, yb - 1);  ymax = max(ymax, yb + NP + 1);
                xmin = min(xmin, xb - 1);  xmax = max(xmax, xb + NP + 1);
            }
            // |shift|<20 -> bounds stay inside the fixed 108x112 stage.
            sbnd[0] = ymin - WROW0;
            sbnd[1] = ymax - WROW0;            // inclusive
            sbnd[2] = (xmin - WCOL0) >> 2;     // first float4 chunk
            sbnd[3] = (xmax - WCOL0) >> 2;     // last float4 chunk
        }
    }
    __syncthreads();

    // ---- Phase 1: stream the dynamic sub-window into smem ----
    {
        const int r_lo = sbnd[0], r_hi = sbnd[1];
        const int q_lo = sbnd[2], q_hi = sbnd[3];
        if (lane >= q_lo && lane <= q_hi) {
            for (int r = r_lo + wid; r <= r_hi; r += 16) {
                uint32_t sdst = smem_u32(stage) + (r * WCOLS + lane * 4) * 4;
                const float* gsrc = I + (WROW0 + r) * MM + WCOL0 + lane * 4;
                asm volatile("cp.async.cg.shared.global [%0], [%1], 16;"
                             :: "r"(sdst), "l"(gsrc) : "memory");
            }
        }
        asm volatile("cp.async.commit_group;" ::: "memory");
        asm volatile("cp.async.wait_group 0;" ::: "memory");
    }
    __syncthreads();

    const int col = threadIdx.y * 2;      // even column of this thread's pair
    const int i0  = threadIdx.z * 8;      // first row of this thread's band
    const int cb  = threadIdx.x * 2;      // first of this thread's 2 channels

    // Per-channel setup. wx shared by the column pair (frac(xx+1)==frac(xx));
    // wy hoisted to a band constant (both validated since R7, continuity of
    // bilinear bounds the ulp effects ~1e-6 << 1e-3).
    float wx[2], wy[2], hp0[2], hp1[2];
    int   qb[2];
    bool  e[2];
#pragma unroll
    for (int u = 0; u < 2; u++) {
        float xx = (float)(col + C0) + spos[cb + u];
        float x0 = floorf(xx);
        wx[u]    = xx - x0;
        int xi   = (int)x0;

        float yy = (float)(i0 + C0) + spos[NC + cb + u];
        float y0 = floorf(yy);
        wy[u]    = yy - y0;
        int yi   = (int)y0;

        int p  = (yi - WROW0) * WCOLS + (xi - WCOL0);
        e[u]   = (p & 1);          // k-invariant parity (WCOLS even)
        qb[u]  = p & ~1;           // 8B-aligned base covering taps p..p+2

        // Top row H-lerp for both columns of the pair.
        float2 A  = *reinterpret_cast<const float2*>(stage + qb[u]);
        float2 Bv = *reinterpret_cast<const float2*>(stage + qb[u] + 2);
        float t0 = e[u] ? A.y  : A.x;
        float t1 = e[u] ? Bv.x : A.y;
        float t2 = e[u] ? Bv.y : Bv.x;
        hp0[u] = fmaf(t1 - t0, wx[u], t0);   // col even
        hp1[u] = fmaf(t2 - t1, wx[u], t1);   // col odd
    }

    // Store base: lane stores the float4 (all 4 channels) of column col+tx.
    const int scol = col + threadIdx.x;
    float4* ob = reinterpret_cast<float4*>(out) +
                 (size_t)b * (NP * NP) + (size_t)i0 * NP + scol;
    const bool tx1 = (threadIdx.x == 1);

#pragma unroll
    for (int k = 0; k < 8; k++) {
        float rE[2], rO[2];       // col-even / col-odd results per channel
#pragma unroll
        for (int u = 0; u < 2; u++) {
            int idx = qb[u] + (k + 1) * WCOLS;
            float2 A  = *reinterpret_cast<const float2*>(stage + idx);
            float2 Bv = *reinterpret_cast<const float2*>(stage + idx + 2);
            float t0 = e[u] ? A.y  : A.x;
            float t1 = e[u] ? Bv.x : A.y;
            float t2 = e[u] ? Bv.y : Bv.x;
            float h0 = fmaf(t1 - t0, wx[u], t0);
            float h1 = fmaf(t2 - t1, wx[u], t1);
            rE[u] = fmaf(h0 - hp0[u], wy[u], hp0[u]);
            rO[u] = fmaf(h1 - hp1[u], wy[u], hp1[u]);
            hp0[u] = h0;  hp1[u] = h1;
        }
        // Pair exchange: tx=0 keeps col-even (ch 0,1) and receives partner's
        // col-even (ch 2,3); tx=1 keeps col-odd (ch 2,3) and receives
        // partner's col-odd (ch 0,1). Send the half we don't keep.
        float s0 = tx1 ? rE[0] : rO[0];
        float s1 = tx1 ? rE[1] : rO[1];
        float g0 = __shfl_xor_sync(0xffffffffu, s0, 1);
        float g1 = __shfl_xor_sync(0xffffffffu, s1, 1);

        float4 res;
        res.x = tx1 ? g0    : rE[0];
        res.y = tx1 ? g1    : rE[1];
        res.z = tx1 ? rO[0] : g0;
        res.w = tx1 ? rO[1] : g1;

        // Warp = 32 consecutive columns -> one contiguous 512B STG.128 run.
        ob[(size_t)k * NP] = res;
    }
}

extern "C" void kernel_launch(void* const* d_in, const int* in_sizes, int n_in,
                              void* d_out, int out_size)
{
    const float* img = (const float*)d_in[0];   // padded_obj (B,128,128,1)
    const float* pos = (const float*)d_in[1];   // positions  (B,1,2,4)
    float* out = (float*)d_out;                 // (B,64,64,4)

    int B = in_sizes[0] / (MM * MM);
    dim3 block(2, 32, 8);
    extract_patches_kernel<<<B, block>>>(img, pos, out);
}